// round 1
// baseline (speedup 1.0000x reference)
#include <cuda_runtime.h>
#include <math.h>

#define H    2048
#define NH   16
#define NKV  4
#define HD   128
#define GROUPS 4
#define S_Q  2048
#define S_E  4096
#define EPS  1e-6f

// ---------------- scratch (no allocation allowed) ----------------
__device__ float g_Q[S_Q * NH * HD];      // 16 MB
__device__ float g_K[S_E * NKV * HD];     // 8 MB
__device__ float g_V[S_E * NKV * HD];     // 8 MB
__device__ float g_AO[S_Q * NH * HD];     // 16 MB

// ---------------- SIMT SGEMM: C[M,N] = A[M,K] @ W[K,N] (+ bias) ----------------
// 128x128 tile, K-step 8, 256 threads, 8x8 micro-tile per thread.
__global__ __launch_bounds__(256) void gemm_bias_kernel(
    const float* __restrict__ A, const float* __restrict__ W,
    const float* __restrict__ bias, float* __restrict__ C,
    int M, int N, int K)
{
    __shared__ float As[8][132];   // transposed: As[k][m]
    __shared__ float Bs[8][132];   // Bs[k][n]

    const int tid = threadIdx.x;
    const int tx = tid & 15;       // 0..15 (N dir)
    const int ty = tid >> 4;       // 0..15 (M dir)
    const int m0 = blockIdx.y * 128;
    const int n0 = blockIdx.x * 128;

    const int arow = tid >> 1;            // 0..127
    const int acol = (tid & 1) * 4;       // 0 or 4
    const int brow = tid >> 5;            // 0..7
    const int bcol = (tid & 31) * 4;      // 0..124

    float acc[8][8];
#pragma unroll
    for (int i = 0; i < 8; i++)
#pragma unroll
        for (int j = 0; j < 8; j++) acc[i][j] = 0.f;

    for (int kk = 0; kk < K; kk += 8) {
        float4 av = *(const float4*)&A[(size_t)(m0 + arow) * K + kk + acol];
        As[acol + 0][arow] = av.x;
        As[acol + 1][arow] = av.y;
        As[acol + 2][arow] = av.z;
        As[acol + 3][arow] = av.w;
        float4 bv = *(const float4*)&W[(size_t)(kk + brow) * N + n0 + bcol];
        *(float4*)&Bs[brow][bcol] = bv;
        __syncthreads();

#pragma unroll
        for (int k = 0; k < 8; k++) {
            float a[8], b[8];
            *(float4*)&a[0] = *(float4*)&As[k][ty * 8];
            *(float4*)&a[4] = *(float4*)&As[k][ty * 8 + 4];
            *(float4*)&b[0] = *(float4*)&Bs[k][tx * 8];
            *(float4*)&b[4] = *(float4*)&Bs[k][tx * 8 + 4];
#pragma unroll
            for (int i = 0; i < 8; i++)
#pragma unroll
                for (int j = 0; j < 8; j++)
                    acc[i][j] += a[i] * b[j];
        }
        __syncthreads();
    }

#pragma unroll
    for (int i = 0; i < 8; i++) {
        const int m = m0 + ty * 8 + i;
#pragma unroll
        for (int j = 0; j < 8; j += 4) {
            const int n = n0 + tx * 8 + j;
            float4 r;
            r.x = acc[i][j + 0];
            r.y = acc[i][j + 1];
            r.z = acc[i][j + 2];
            r.w = acc[i][j + 3];
            if (bias) {
                r.x += bias[n + 0]; r.y += bias[n + 1];
                r.z += bias[n + 2]; r.w += bias[n + 3];
            }
            *(float4*)&C[(size_t)m * N + n] = r;
        }
    }
}

// ---------------- per-head RMSNorm (in place), one block per 128-elem segment ----------------
__global__ __launch_bounds__(128) void rmsnorm_kernel(float* __restrict__ x,
                                                      const float* __restrict__ w)
{
    float* p = x + (size_t)blockIdx.x * HD;
    const int t = threadIdx.x;
    float v = p[t];
    float sq = v * v;
#pragma unroll
    for (int m = 16; m >= 1; m >>= 1)
        sq += __shfl_xor_sync(0xffffffffu, sq, m);
    __shared__ float red[4];
    if ((t & 31) == 0) red[t >> 5] = sq;
    __syncthreads();
    float tot = red[0] + red[1] + red[2] + red[3];
    float inv = rsqrtf(tot * (1.0f / HD) + EPS);
    p[t] = v * inv * w[t];
}

// ---------------- flash attention (fp32, online softmax, GQA, mask) ----------------
// Block: 256 threads, q-tile 64 rows, kv-tile 64 rows.
// smem: Qs[64][132], KV buffer (K transposed [128][68] / V [64][132]), Ss[64][68]
#define QT 64
#define ET 64
#define QS_LD 132
#define KT_LD 68
#define SS_LD 68
#define SMEM_FLOATS (QT * QS_LD + HD * KT_LD + QT * SS_LD)
#define SMEM_BYTES  (SMEM_FLOATS * 4)

__global__ __launch_bounds__(256) void flash_kernel(
    const float* __restrict__ Q, const float* __restrict__ Kb,
    const float* __restrict__ Vb, const float* __restrict__ mask,
    float* __restrict__ AO)
{
    extern __shared__ float sm[];
    float* Qs = sm;                         // [QT][QS_LD]
    float* KV = sm + QT * QS_LD;            // K: [HD][KT_LD] (transposed) / V: [ET][QS_LD-ish, use 132]
    float* Ss = sm + QT * QS_LD + HD * KT_LD; // [QT][SS_LD]

    const int h = blockIdx.y;
    const int kh = h / GROUPS;
    const int q0 = blockIdx.x * QT;
    const int tid = threadIdx.x;
    const int tx = tid & 15;   // 0..15
    const int ty = tid >> 4;   // 0..15

    // load Q tile
    for (int i = tid; i < QT * (HD / 4); i += 256) {
        int r = i >> 5;            // /32
        int c4 = (i & 31) * 4;
        float4 v = *(const float4*)&Q[(size_t)(q0 + r) * (NH * HD) + h * HD + c4];
        *(float4*)&Qs[r * QS_LD + c4] = v;
    }

    const float scale = 0.08838834764831845f;   // 1/sqrt(128)
    float m_i[4], l_i[4], o[4][8];
#pragma unroll
    for (int i = 0; i < 4; i++) {
        m_i[i] = -INFINITY; l_i[i] = 0.f;
#pragma unroll
        for (int c = 0; c < 8; c++) o[i][c] = 0.f;
    }

    for (int e0 = 0; e0 < S_E; e0 += ET) {
        __syncthreads();   // previous iter's KV(V) / Ss reads done
        // load K tile, transposed: KV[c][r] = K[(e0+r)][kh*HD + c]
        for (int i = tid; i < ET * (HD / 4); i += 256) {
            int r = i >> 5;
            int c4 = (i & 31) * 4;
            float4 v = *(const float4*)&Kb[(size_t)(e0 + r) * (NKV * HD) + kh * HD + c4];
            KV[(c4 + 0) * KT_LD + r] = v.x;
            KV[(c4 + 1) * KT_LD + r] = v.y;
            KV[(c4 + 2) * KT_LD + r] = v.z;
            KV[(c4 + 3) * KT_LD + r] = v.w;
        }
        __syncthreads();

        // S = Q @ K^T  -> s[4][4], rows ty*4+i, cols tx*4+j
        float s[4][4];
#pragma unroll
        for (int i = 0; i < 4; i++)
#pragma unroll
            for (int j = 0; j < 4; j++) s[i][j] = 0.f;

        for (int k = 0; k < HD; k += 4) {
            float4 kvv[4];
#pragma unroll
            for (int kk = 0; kk < 4; kk++)
                kvv[kk] = *(float4*)&KV[(k + kk) * KT_LD + tx * 4];
            float4 qv[4];
#pragma unroll
            for (int i = 0; i < 4; i++)
                qv[i] = *(float4*)&Qs[(ty * 4 + i) * QS_LD + k];
#pragma unroll
            for (int i = 0; i < 4; i++) {
                const float qa[4] = {qv[i].x, qv[i].y, qv[i].z, qv[i].w};
#pragma unroll
                for (int kk = 0; kk < 4; kk++) {
                    s[i][0] += qa[kk] * kvv[kk].x;
                    s[i][1] += qa[kk] * kvv[kk].y;
                    s[i][2] += qa[kk] * kvv[kk].z;
                    s[i][3] += qa[kk] * kvv[kk].w;
                }
            }
        }

        // scale + mask, online softmax update
#pragma unroll
        for (int i = 0; i < 4; i++) {
            const int qr = q0 + ty * 4 + i;
            const float* mrow = &mask[(size_t)qr * S_E + e0 + tx * 4];
            float t0 = s[i][0] * scale + mrow[0];
            float t1 = s[i][1] * scale + mrow[1];
            float t2 = s[i][2] * scale + mrow[2];
            float t3 = s[i][3] * scale + mrow[3];
            float rm = fmaxf(fmaxf(t0, t1), fmaxf(t2, t3));
#pragma unroll
            for (int msk = 8; msk >= 1; msk >>= 1)
                rm = fmaxf(rm, __shfl_xor_sync(0xffffffffu, rm, msk));
            float m_new = fmaxf(m_i[i], rm);
            float corr = __expf(m_i[i] - m_new);
            float p0 = __expf(t0 - m_new);
            float p1 = __expf(t1 - m_new);
            float p2 = __expf(t2 - m_new);
            float p3 = __expf(t3 - m_new);
            float rs = p0 + p1 + p2 + p3;
#pragma unroll
            for (int msk = 8; msk >= 1; msk >>= 1)
                rs += __shfl_xor_sync(0xffffffffu, rs, msk);
            l_i[i] = l_i[i] * corr + rs;
            m_i[i] = m_new;
#pragma unroll
            for (int c = 0; c < 8; c++) o[i][c] *= corr;
            Ss[(ty * 4 + i) * SS_LD + tx * 4 + 0] = p0;
            Ss[(ty * 4 + i) * SS_LD + tx * 4 + 1] = p1;
            Ss[(ty * 4 + i) * SS_LD + tx * 4 + 2] = p2;
            Ss[(ty * 4 + i) * SS_LD + tx * 4 + 3] = p3;
        }
        __syncthreads();  // Ss complete, K-reads of KV complete

        // load V tile: KV[r][c] = V[(e0+r)][kh*HD + c]  (row stride 132)
        for (int i = tid; i < ET * (HD / 4); i += 256) {
            int r = i >> 5;
            int c4 = (i & 31) * 4;
            float4 v = *(const float4*)&Vb[(size_t)(e0 + r) * (NKV * HD) + kh * HD + c4];
            *(float4*)&KV[r * 132 + c4] = v;
        }
        __syncthreads();

        // O += P @ V : o[i][c], c block = tx*8
        for (int j = 0; j < ET; j++) {
            float4 v0 = *(float4*)&KV[j * 132 + tx * 8];
            float4 v1 = *(float4*)&KV[j * 132 + tx * 8 + 4];
            const float vv[8] = {v0.x, v0.y, v0.z, v0.w, v1.x, v1.y, v1.z, v1.w};
#pragma unroll
            for (int i = 0; i < 4; i++) {
                float p = Ss[(ty * 4 + i) * SS_LD + j];
#pragma unroll
                for (int c = 0; c < 8; c++) o[i][c] += p * vv[c];
            }
        }
    }

    // epilogue
#pragma unroll
    for (int i = 0; i < 4; i++) {
        float inv = 1.0f / l_i[i];
        const int qr = q0 + ty * 4 + i;
#pragma unroll
        for (int c = 0; c < 8; c += 4) {
            float4 r;
            r.x = o[i][c + 0] * inv;
            r.y = o[i][c + 1] * inv;
            r.z = o[i][c + 2] * inv;
            r.w = o[i][c + 3] * inv;
            *(float4*)&AO[(size_t)qr * (NH * HD) + h * HD + tx * 8 + c] = r;
        }
    }
}

// ---------------- launch ----------------
extern "C" void kernel_launch(void* const* d_in, const int* in_sizes, int n_in,
                              void* d_out, int out_size)
{
    const float* hs   = (const float*)d_in[0];
    const float* ehs  = (const float*)d_in[1];
    const float* mask = (const float*)d_in[2];
    const float* Wq   = (const float*)d_in[3];
    const float* bq   = (const float*)d_in[4];
    const float* Wk   = (const float*)d_in[5];
    const float* bk   = (const float*)d_in[6];
    const float* Wv   = (const float*)d_in[7];
    const float* bv   = (const float*)d_in[8];
    const float* Wo   = (const float*)d_in[9];
    const float* qn   = (const float*)d_in[10];
    const float* kn   = (const float*)d_in[11];
    float* out = (float*)d_out;

    float *Qb, *Kb, *Vb, *AOb;
    cudaGetSymbolAddress((void**)&Qb, g_Q);
    cudaGetSymbolAddress((void**)&Kb, g_K);
    cudaGetSymbolAddress((void**)&Vb, g_V);
    cudaGetSymbolAddress((void**)&AOb, g_AO);

    cudaFuncSetAttribute(flash_kernel,
                         cudaFuncAttributeMaxDynamicSharedMemorySize, SMEM_BYTES);

    // projections
    gemm_bias_kernel<<<dim3(NH * HD / 128, S_Q / 128), 256>>>(hs, Wq, bq, Qb, S_Q, NH * HD, H);
    gemm_bias_kernel<<<dim3(NKV * HD / 128, S_E / 128), 256>>>(ehs, Wk, bk, Kb, S_E, NKV * HD, H);
    gemm_bias_kernel<<<dim3(NKV * HD / 128, S_E / 128), 256>>>(ehs, Wv, bv, Vb, S_E, NKV * HD, H);

    // per-head RMSNorm
    rmsnorm_kernel<<<S_Q * NH, 128>>>(Qb, qn);
    rmsnorm_kernel<<<S_E * NKV, 128>>>(Kb, kn);

    // attention
    flash_kernel<<<dim3(S_Q / QT, NH), 256, SMEM_BYTES>>>(Qb, Kb, Vb, mask, AOb);

    // output projection
    gemm_bias_kernel<<<dim3(H / 128, S_Q / 128), 256>>>(AOb, Wo, nullptr, out, S_Q, H, NH * HD);
}

// round 2
// speedup vs baseline: 1.8788x; 1.8788x over previous
#include <cuda_runtime.h>
#include <cuda_bf16.h>
#include <math.h>

#define H    2048
#define NH   16
#define NKV  4
#define HD   128
#define S_Q  2048
#define S_E  4096
#define EPS  1e-6f

// ---------------- scratch ----------------
__device__ float g_Q[S_Q * NH * HD];
__device__ float g_K[S_E * NKV * HD];
__device__ float g_V[S_E * NKV * HD];
__device__ float g_AO[S_Q * NH * HD];

// ---------------- mma / ldmatrix helpers ----------------
__device__ __forceinline__ unsigned smaddr(const void* p) {
    return (unsigned)__cvta_generic_to_shared(p);
}
__device__ __forceinline__ void ldm_x4(unsigned& r0, unsigned& r1, unsigned& r2, unsigned& r3,
                                       unsigned addr) {
    asm volatile("ldmatrix.sync.aligned.m8n8.x4.shared.b16 {%0,%1,%2,%3},[%4];\n"
                 : "=r"(r0), "=r"(r1), "=r"(r2), "=r"(r3) : "r"(addr));
}
__device__ __forceinline__ void ldm_x2(unsigned& r0, unsigned& r1, unsigned addr) {
    asm volatile("ldmatrix.sync.aligned.m8n8.x2.shared.b16 {%0,%1},[%2];\n"
                 : "=r"(r0), "=r"(r1) : "r"(addr));
}
__device__ __forceinline__ void mma16816(float* c, unsigned a0, unsigned a1, unsigned a2,
                                         unsigned a3, unsigned b0, unsigned b1) {
    asm volatile(
        "mma.sync.aligned.m16n8k16.row.col.f32.bf16.bf16.f32 "
        "{%0,%1,%2,%3},{%4,%5,%6,%7},{%8,%9},{%0,%1,%2,%3};\n"
        : "+f"(c[0]), "+f"(c[1]), "+f"(c[2]), "+f"(c[3])
        : "r"(a0), "r"(a1), "r"(a2), "r"(a3), "r"(b0), "r"(b1));
}
// acc += Ahi*Bhi + Ahi*Blo + Alo*Bhi   (bf16x3 fp32 emulation)
__device__ __forceinline__ void mma3(float* c, const unsigned* ah, const unsigned* al,
                                     unsigned bh0, unsigned bh1, unsigned bl0, unsigned bl1) {
    mma16816(c, ah[0], ah[1], ah[2], ah[3], bh0, bh1);
    mma16816(c, ah[0], ah[1], ah[2], ah[3], bl0, bl1);
    mma16816(c, al[0], al[1], al[2], al[3], bh0, bh1);
}
__device__ __forceinline__ unsigned pack2(float x, float y) {
    __nv_bfloat162 t;
    t.x = __float2bfloat16(x);
    t.y = __float2bfloat16(y);
    return *(unsigned*)&t;
}

// ---------------- GEMM: C[M,N] = A[M,K] @ W[K,N] (+bias), bf16x3 ----------------
// 128x128 CTA tile, K-step 32, 8 warps in 2(M)x4(N), warp tile 64x32.
__global__ __launch_bounds__(256) void gemm_bias_x3(
    const float* __restrict__ A, const float* __restrict__ W,
    const float* __restrict__ bias, float* __restrict__ C,
    int M, int N, int K)
{
    // pitch 20 u32 per row (16 u32 of data); 20 % 8 == 4 -> conflict-free ldmatrix
    __shared__ unsigned sAhi[128 * 20], sAlo[128 * 20];
    __shared__ unsigned sBhi[128 * 20], sBlo[128 * 20];   // B stored [n][k]

    const int tid  = threadIdx.x;
    const int lane = tid & 31;
    const int warp = tid >> 5;
    const int wm   = warp >> 2;          // 0..1
    const int wn   = warp & 3;           // 0..3
    const int g    = lane >> 2;
    const int th   = lane & 3;
    const int m0   = blockIdx.y * 128;
    const int n0   = blockIdx.x * 128;

    float acc[4][4][4];
#pragma unroll
    for (int i = 0; i < 4; i++)
#pragma unroll
        for (int j = 0; j < 4; j++)
#pragma unroll
            for (int c = 0; c < 4; c++) acc[i][j][c] = 0.f;

    float4 aR[4], bR[4];
#pragma unroll
    for (int l = 0; l < 4; l++) {
        int gi = l * 256 + tid;
        int ar = gi >> 3, ac = (gi & 7) * 4;
        aR[l] = *(const float4*)&A[(size_t)(m0 + ar) * K + ac];
        int br = gi >> 5, bc = (gi & 31) * 4;
        bR[l] = *(const float4*)&W[(size_t)br * N + n0 + bc];
    }

    const int nK = K / 32;
    for (int kt = 0; kt < nK; kt++) {
        // convert + store to smem
#pragma unroll
        for (int l = 0; l < 4; l++) {
            int gi = l * 256 + tid;
            int ar = gi >> 3, ac = (gi & 7) * 4;
            float4 v = aR[l];
            __nv_bfloat16 h0 = __float2bfloat16(v.x), h1 = __float2bfloat16(v.y);
            __nv_bfloat16 h2 = __float2bfloat16(v.z), h3 = __float2bfloat16(v.w);
            __nv_bfloat162 p0, p1, q0, q1;
            p0.x = h0; p0.y = h1; p1.x = h2; p1.y = h3;
            q0.x = __float2bfloat16(v.x - __bfloat162float(h0));
            q0.y = __float2bfloat16(v.y - __bfloat162float(h1));
            q1.x = __float2bfloat16(v.z - __bfloat162float(h2));
            q1.y = __float2bfloat16(v.w - __bfloat162float(h3));
            sAhi[ar * 20 + (ac >> 1)]     = *(unsigned*)&p0;
            sAhi[ar * 20 + (ac >> 1) + 1] = *(unsigned*)&p1;
            sAlo[ar * 20 + (ac >> 1)]     = *(unsigned*)&q0;
            sAlo[ar * 20 + (ac >> 1) + 1] = *(unsigned*)&q1;

            int br = gi >> 5, bc = (gi & 31) * 4;
            float4 w = bR[l];
            float wv[4] = {w.x, w.y, w.z, w.w};
            __nv_bfloat16* bh = (__nv_bfloat16*)sBhi;
            __nv_bfloat16* bl = (__nv_bfloat16*)sBlo;
#pragma unroll
            for (int j = 0; j < 4; j++) {
                __nv_bfloat16 hh = __float2bfloat16(wv[j]);
                bh[(bc + j) * 40 + br] = hh;
                bl[(bc + j) * 40 + br] = __float2bfloat16(wv[j] - __bfloat162float(hh));
            }
        }
        __syncthreads();
        if (kt + 1 < nK) {
#pragma unroll
            for (int l = 0; l < 4; l++) {
                int gi = l * 256 + tid;
                int ar = gi >> 3, ac = (gi & 7) * 4;
                aR[l] = *(const float4*)&A[(size_t)(m0 + ar) * K + (kt + 1) * 32 + ac];
                int br = gi >> 5, bc = (gi & 31) * 4;
                bR[l] = *(const float4*)&W[(size_t)((kt + 1) * 32 + br) * N + n0 + bc];
            }
        }
        // compute 2 k16 steps
#pragma unroll
        for (int ks = 0; ks < 2; ks++) {
            unsigned ahi[4][4], alo[4][4];
            const int rowl = wm * 64 + (lane & 15);
            const int colu = ks * 8 + (lane >> 4) * 4;
#pragma unroll
            for (int mt = 0; mt < 4; mt++) {
                ldm_x4(ahi[mt][0], ahi[mt][1], ahi[mt][2], ahi[mt][3],
                       smaddr(&sAhi[(rowl + mt * 16) * 20 + colu]));
                ldm_x4(alo[mt][0], alo[mt][1], alo[mt][2], alo[mt][3],
                       smaddr(&sAlo[(rowl + mt * 16) * 20 + colu]));
            }
            const int rowb = lane & 7;
            const int colb = ks * 8 + ((lane >> 3) & 1) * 4;
#pragma unroll
            for (int nt = 0; nt < 4; nt++) {
                unsigned bh0, bh1, bl0, bl1;
                ldm_x2(bh0, bh1, smaddr(&sBhi[(wn * 32 + nt * 8 + rowb) * 20 + colb]));
                ldm_x2(bl0, bl1, smaddr(&sBlo[(wn * 32 + nt * 8 + rowb) * 20 + colb]));
#pragma unroll
                for (int mt = 0; mt < 4; mt++)
                    mma3(acc[mt][nt], ahi[mt], alo[mt], bh0, bh1, bl0, bl1);
            }
        }
        __syncthreads();
    }

    // epilogue
#pragma unroll
    for (int mt = 0; mt < 4; mt++) {
        int r0 = m0 + wm * 64 + mt * 16 + g;
#pragma unroll
        for (int nt = 0; nt < 4; nt++) {
            int cc = n0 + wn * 32 + nt * 8 + th * 2;
            float b0 = 0.f, b1 = 0.f;
            if (bias) { b0 = bias[cc]; b1 = bias[cc + 1]; }
            float2 v0 = {acc[mt][nt][0] + b0, acc[mt][nt][1] + b1};
            float2 v1 = {acc[mt][nt][2] + b0, acc[mt][nt][3] + b1};
            *(float2*)&C[(size_t)r0 * N + cc] = v0;
            *(float2*)&C[(size_t)(r0 + 8) * N + cc] = v1;
        }
    }
}

// ---------------- per-head RMSNorm ----------------
__global__ __launch_bounds__(128) void rmsnorm_kernel(float* __restrict__ x,
                                                      const float* __restrict__ w)
{
    float* p = x + (size_t)blockIdx.x * HD;
    const int t = threadIdx.x;
    float v = p[t];
    float sq = v * v;
#pragma unroll
    for (int m = 16; m >= 1; m >>= 1)
        sq += __shfl_xor_sync(0xffffffffu, sq, m);
    __shared__ float red[4];
    if ((t & 31) == 0) red[t >> 5] = sq;
    __syncthreads();
    float tot = red[0] + red[1] + red[2] + red[3];
    float inv = rsqrtf(tot * (1.0f / HD) + EPS);
    p[t] = v * inv * w[t];
}

// ---------------- flash attention, bf16x3 mma ----------------
// CTA: 128 q rows, 4 warps (32 rows each = 2 m-tiles), kv-tile 32.
#define FL_SMEM_U32 (2 * (128 * 68) + 2 * (32 * 68) + 2 * (128 * 20))
#define FL_SMEM_BYTES (FL_SMEM_U32 * 4)

__global__ __launch_bounds__(128) void flash_x3(
    const float* __restrict__ Q, const float* __restrict__ Kg,
    const float* __restrict__ Vg, const float* __restrict__ mask,
    float* __restrict__ AO)
{
    extern __shared__ unsigned smbuf[];
    unsigned* sQhi = smbuf;                    // [128][68]  (pair cols of HD)
    unsigned* sQlo = sQhi + 128 * 68;
    unsigned* sKhi = sQlo + 128 * 68;          // [32][68]   (n=kv, k=HD)
    unsigned* sKlo = sKhi + 32 * 68;
    unsigned* sVhi = sKlo + 32 * 68;           // [128][20]  (n=hd, k=kv pairs)
    unsigned* sVlo = sVhi + 128 * 20;

    const int h  = blockIdx.y;
    const int kh = h >> 2;
    const int q0 = blockIdx.x * 128;
    const int tid  = threadIdx.x;
    const int lane = tid & 31;
    const int wm   = tid >> 5;      // warp id = q sub-block
    const int g    = lane >> 2;
    const int th   = lane & 3;

    // ---- load Q tile (once), split hi/lo ----
#pragma unroll 4
    for (int l = 0; l < 32; l++) {
        int gi = l * 128 + tid;
        int row = gi >> 5, c4 = (gi & 31) * 4;
        float4 v = *(const float4*)&Q[(size_t)(q0 + row) * (NH * HD) + h * HD + c4];
        __nv_bfloat162 p0, p1, q0_, q1_;
        p0.x = __float2bfloat16(v.x); p0.y = __float2bfloat16(v.y);
        p1.x = __float2bfloat16(v.z); p1.y = __float2bfloat16(v.w);
        q0_.x = __float2bfloat16(v.x - __bfloat162float(p0.x));
        q0_.y = __float2bfloat16(v.y - __bfloat162float(p0.y));
        q1_.x = __float2bfloat16(v.z - __bfloat162float(p1.x));
        q1_.y = __float2bfloat16(v.w - __bfloat162float(p1.y));
        sQhi[row * 68 + (c4 >> 1)]     = *(unsigned*)&p0;
        sQhi[row * 68 + (c4 >> 1) + 1] = *(unsigned*)&p1;
        sQlo[row * 68 + (c4 >> 1)]     = *(unsigned*)&q0_;
        sQlo[row * 68 + (c4 >> 1) + 1] = *(unsigned*)&q1_;
    }

    const float scale = 0.08838834764831845f;   // 1/sqrt(128)
    float o[2][16][4];
    float m_i[4], l_i[4];
#pragma unroll
    for (int mt = 0; mt < 2; mt++)
#pragma unroll
        for (int nt = 0; nt < 16; nt++)
#pragma unroll
            for (int c = 0; c < 4; c++) o[mt][nt][c] = 0.f;
#pragma unroll
    for (int i = 0; i < 4; i++) { m_i[i] = -INFINITY; l_i[i] = 0.f; }

    for (int e0 = 0; e0 < S_E; e0 += 32) {
        __syncthreads();
        // ---- load K (natural [n][k]) and V (transposed [hd][e]) ----
#pragma unroll
        for (int l = 0; l < 8; l++) {
            int gi = l * 128 + tid;
            int row = gi >> 5, c4 = (gi & 31) * 4;
            float4 kv = *(const float4*)&Kg[(size_t)(e0 + row) * (NKV * HD) + kh * HD + c4];
            __nv_bfloat162 p0, p1, q0_, q1_;
            p0.x = __float2bfloat16(kv.x); p0.y = __float2bfloat16(kv.y);
            p1.x = __float2bfloat16(kv.z); p1.y = __float2bfloat16(kv.w);
            q0_.x = __float2bfloat16(kv.x - __bfloat162float(p0.x));
            q0_.y = __float2bfloat16(kv.y - __bfloat162float(p0.y));
            q1_.x = __float2bfloat16(kv.z - __bfloat162float(p1.x));
            q1_.y = __float2bfloat16(kv.w - __bfloat162float(p1.y));
            sKhi[row * 68 + (c4 >> 1)]     = *(unsigned*)&p0;
            sKhi[row * 68 + (c4 >> 1) + 1] = *(unsigned*)&p1;
            sKlo[row * 68 + (c4 >> 1)]     = *(unsigned*)&q0_;
            sKlo[row * 68 + (c4 >> 1) + 1] = *(unsigned*)&q1_;

            float4 vv = *(const float4*)&Vg[(size_t)(e0 + row) * (NKV * HD) + kh * HD + c4];
            float va[4] = {vv.x, vv.y, vv.z, vv.w};
            __nv_bfloat16* vh = (__nv_bfloat16*)sVhi;
            __nv_bfloat16* vl = (__nv_bfloat16*)sVlo;
#pragma unroll
            for (int j = 0; j < 4; j++) {
                __nv_bfloat16 hh = __float2bfloat16(va[j]);
                vh[(c4 + j) * 40 + row] = hh;
                vl[(c4 + j) * 40 + row] = __float2bfloat16(va[j] - __bfloat162float(hh));
            }
        }
        __syncthreads();

        // ---- S = Q K^T ----
        float s[2][4][4];
#pragma unroll
        for (int mt = 0; mt < 2; mt++)
#pragma unroll
            for (int nt = 0; nt < 4; nt++)
#pragma unroll
                for (int c = 0; c < 4; c++) s[mt][nt][c] = 0.f;

#pragma unroll
        for (int ks = 0; ks < 8; ks++) {
            unsigned ahi[2][4], alo[2][4];
            const int rowl = wm * 32 + (lane & 15);
            const int colu = ks * 8 + (lane >> 4) * 4;
#pragma unroll
            for (int mt = 0; mt < 2; mt++) {
                ldm_x4(ahi[mt][0], ahi[mt][1], ahi[mt][2], ahi[mt][3],
                       smaddr(&sQhi[(rowl + mt * 16) * 68 + colu]));
                ldm_x4(alo[mt][0], alo[mt][1], alo[mt][2], alo[mt][3],
                       smaddr(&sQlo[(rowl + mt * 16) * 68 + colu]));
            }
            const int rowb = lane & 7;
            const int colb = ks * 8 + ((lane >> 3) & 1) * 4;
#pragma unroll
            for (int nt = 0; nt < 4; nt++) {
                unsigned bh0, bh1, bl0, bl1;
                ldm_x2(bh0, bh1, smaddr(&sKhi[(nt * 8 + rowb) * 68 + colb]));
                ldm_x2(bl0, bl1, smaddr(&sKlo[(nt * 8 + rowb) * 68 + colb]));
#pragma unroll
                for (int mt = 0; mt < 2; mt++)
                    mma3(s[mt][nt], ahi[mt], alo[mt], bh0, bh1, bl0, bl1);
            }
        }

        // ---- softmax (rows fully within th-quad) ----
#pragma unroll
        for (int mt = 0; mt < 2; mt++) {
            const int r0 = q0 + wm * 32 + mt * 16 + g;
            // scale + mask
#pragma unroll
            for (int nt = 0; nt < 4; nt++) {
                const int cb = e0 + nt * 8 + th * 2;
                float2 mk0 = *(const float2*)&mask[(size_t)r0 * S_E + cb];
                float2 mk1 = *(const float2*)&mask[(size_t)(r0 + 8) * S_E + cb];
                s[mt][nt][0] = s[mt][nt][0] * scale + mk0.x;
                s[mt][nt][1] = s[mt][nt][1] * scale + mk0.y;
                s[mt][nt][2] = s[mt][nt][2] * scale + mk1.x;
                s[mt][nt][3] = s[mt][nt][3] * scale + mk1.y;
            }
            float mx0 = -INFINITY, mx1 = -INFINITY;
#pragma unroll
            for (int nt = 0; nt < 4; nt++) {
                mx0 = fmaxf(mx0, fmaxf(s[mt][nt][0], s[mt][nt][1]));
                mx1 = fmaxf(mx1, fmaxf(s[mt][nt][2], s[mt][nt][3]));
            }
            mx0 = fmaxf(mx0, __shfl_xor_sync(0xffffffffu, mx0, 1));
            mx0 = fmaxf(mx0, __shfl_xor_sync(0xffffffffu, mx0, 2));
            mx1 = fmaxf(mx1, __shfl_xor_sync(0xffffffffu, mx1, 1));
            mx1 = fmaxf(mx1, __shfl_xor_sync(0xffffffffu, mx1, 2));
            float mn0 = fmaxf(m_i[mt * 2 + 0], mx0);
            float mn1 = fmaxf(m_i[mt * 2 + 1], mx1);
            float cr0 = __expf(m_i[mt * 2 + 0] - mn0);
            float cr1 = __expf(m_i[mt * 2 + 1] - mn1);
            m_i[mt * 2 + 0] = mn0;
            m_i[mt * 2 + 1] = mn1;
            float sm0 = 0.f, sm1 = 0.f;
#pragma unroll
            for (int nt = 0; nt < 4; nt++) {
                s[mt][nt][0] = __expf(s[mt][nt][0] - mn0);
                s[mt][nt][1] = __expf(s[mt][nt][1] - mn0);
                s[mt][nt][2] = __expf(s[mt][nt][2] - mn1);
                s[mt][nt][3] = __expf(s[mt][nt][3] - mn1);
                sm0 += s[mt][nt][0] + s[mt][nt][1];
                sm1 += s[mt][nt][2] + s[mt][nt][3];
            }
            sm0 += __shfl_xor_sync(0xffffffffu, sm0, 1);
            sm0 += __shfl_xor_sync(0xffffffffu, sm0, 2);
            sm1 += __shfl_xor_sync(0xffffffffu, sm1, 1);
            sm1 += __shfl_xor_sync(0xffffffffu, sm1, 2);
            l_i[mt * 2 + 0] = l_i[mt * 2 + 0] * cr0 + sm0;
            l_i[mt * 2 + 1] = l_i[mt * 2 + 1] * cr1 + sm1;
#pragma unroll
            for (int nt = 0; nt < 16; nt++) {
                o[mt][nt][0] *= cr0;
                o[mt][nt][1] *= cr0;
                o[mt][nt][2] *= cr1;
                o[mt][nt][3] *= cr1;
            }
        }

        // ---- O += P V ----
#pragma unroll
        for (int ks2 = 0; ks2 < 2; ks2++) {
            unsigned phi[2][4], plo[2][4];
#pragma unroll
            for (int mt = 0; mt < 2; mt++) {
                const float* sa = s[mt][2 * ks2];
                const float* sb = s[mt][2 * ks2 + 1];
                phi[mt][0] = pack2(sa[0], sa[1]);
                phi[mt][1] = pack2(sa[2], sa[3]);
                phi[mt][2] = pack2(sb[0], sb[1]);
                phi[mt][3] = pack2(sb[2], sb[3]);
                __nv_bfloat162 t0 = *(__nv_bfloat162*)&phi[mt][0];
                __nv_bfloat162 t1 = *(__nv_bfloat162*)&phi[mt][1];
                __nv_bfloat162 t2 = *(__nv_bfloat162*)&phi[mt][2];
                __nv_bfloat162 t3 = *(__nv_bfloat162*)&phi[mt][3];
                plo[mt][0] = pack2(sa[0] - __bfloat162float(t0.x), sa[1] - __bfloat162float(t0.y));
                plo[mt][1] = pack2(sa[2] - __bfloat162float(t1.x), sa[3] - __bfloat162float(t1.y));
                plo[mt][2] = pack2(sb[0] - __bfloat162float(t2.x), sb[1] - __bfloat162float(t2.y));
                plo[mt][3] = pack2(sb[2] - __bfloat162float(t3.x), sb[3] - __bfloat162float(t3.y));
            }
            const int rowv = lane & 7;
            const int colv = ks2 * 8 + ((lane >> 3) & 1) * 4;
#pragma unroll
            for (int nt2 = 0; nt2 < 16; nt2++) {
                unsigned vh0, vh1, vl0, vl1;
                ldm_x2(vh0, vh1, smaddr(&sVhi[(nt2 * 8 + rowv) * 20 + colv]));
                ldm_x2(vl0, vl1, smaddr(&sVlo[(nt2 * 8 + rowv) * 20 + colv]));
#pragma unroll
                for (int mt = 0; mt < 2; mt++)
                    mma3(o[mt][nt2], phi[mt], plo[mt], vh0, vh1, vl0, vl1);
            }
        }
    }

    // ---- epilogue ----
#pragma unroll
    for (int mt = 0; mt < 2; mt++) {
        const int r0 = q0 + wm * 32 + mt * 16 + g;
        const float inv0 = 1.0f / l_i[mt * 2 + 0];
        const float inv1 = 1.0f / l_i[mt * 2 + 1];
#pragma unroll
        for (int nt2 = 0; nt2 < 16; nt2++) {
            const int cc = h * HD + nt2 * 8 + th * 2;
            float2 v0 = {o[mt][nt2][0] * inv0, o[mt][nt2][1] * inv0};
            float2 v1 = {o[mt][nt2][2] * inv1, o[mt][nt2][3] * inv1};
            *(float2*)&AO[(size_t)r0 * (NH * HD) + cc] = v0;
            *(float2*)&AO[(size_t)(r0 + 8) * (NH * HD) + cc] = v1;
        }
    }
}

// ---------------- launch ----------------
extern "C" void kernel_launch(void* const* d_in, const int* in_sizes, int n_in,
                              void* d_out, int out_size)
{
    const float* hs   = (const float*)d_in[0];
    const float* ehs  = (const float*)d_in[1];
    const float* mask = (const float*)d_in[2];
    const float* Wq   = (const float*)d_in[3];
    const float* bq   = (const float*)d_in[4];
    const float* Wk   = (const float*)d_in[5];
    const float* bk   = (const float*)d_in[6];
    const float* Wv   = (const float*)d_in[7];
    const float* bv   = (const float*)d_in[8];
    const float* Wo   = (const float*)d_in[9];
    const float* qn   = (const float*)d_in[10];
    const float* kn   = (const float*)d_in[11];
    float* out = (float*)d_out;

    float *Qb, *Kb, *Vb, *AOb;
    cudaGetSymbolAddress((void**)&Qb, g_Q);
    cudaGetSymbolAddress((void**)&Kb, g_K);
    cudaGetSymbolAddress((void**)&Vb, g_V);
    cudaGetSymbolAddress((void**)&AOb, g_AO);

    cudaFuncSetAttribute(flash_x3, cudaFuncAttributeMaxDynamicSharedMemorySize, FL_SMEM_BYTES);

    gemm_bias_x3<<<dim3(NH * HD / 128, S_Q / 128), 256>>>(hs, Wq, bq, Qb, S_Q, NH * HD, H);
    gemm_bias_x3<<<dim3(NKV * HD / 128, S_E / 128), 256>>>(ehs, Wk, bk, Kb, S_E, NKV * HD, H);
    gemm_bias_x3<<<dim3(NKV * HD / 128, S_E / 128), 256>>>(ehs, Wv, bv, Vb, S_E, NKV * HD, H);

    rmsnorm_kernel<<<S_Q * NH, 128>>>(Qb, qn);
    rmsnorm_kernel<<<S_E * NKV, 128>>>(Kb, kn);

    flash_x3<<<dim3(S_Q / 128, NH), 128, FL_SMEM_BYTES>>>(Qb, Kb, Vb, mask, AOb);

    gemm_bias_x3<<<dim3(H / 128, S_Q / 128), 256>>>(AOb, Wo, nullptr, out, S_Q, H, NH * HD);
}

// round 3
// speedup vs baseline: 3.5918x; 1.9118x over previous
#include <cuda_runtime.h>
#include <cuda_bf16.h>
#include <math.h>

#define H    2048
#define NH   16
#define NKV  4
#define HD   128
#define S_Q  2048
#define S_E  4096
#define EPS  1e-6f

typedef __nv_bfloat16 bf16;
typedef __nv_bfloat162 bf162;

// ---------------- scratch (split bf16) ----------------
__device__ bf16 g_hsH[S_Q * H],    g_hsL[S_Q * H];
__device__ bf16 g_ehsH[S_E * H],   g_ehsL[S_E * H];
__device__ bf16 g_WqTH[H * H],     g_WqTL[H * H];          // [N=2048][K=2048]
__device__ bf16 g_WkTH[512 * H],   g_WkTL[512 * H];        // [512][2048]
__device__ bf16 g_WvTH[512 * H],   g_WvTL[512 * H];
__device__ bf16 g_WoTH[H * H],     g_WoTL[H * H];
__device__ bf16 g_QH[S_Q * H],     g_QL[S_Q * H];          // normed Q
__device__ bf16 g_KH[S_E * 512],   g_KL[S_E * 512];        // normed K
__device__ bf16 g_VTH[512 * S_E],  g_VTL[512 * S_E];       // V transposed [hd][e]
__device__ bf16 g_AOH[S_Q * H],    g_AOL[S_Q * H];

// ---------------- helpers ----------------
__device__ __forceinline__ unsigned smaddr(const void* p) {
    return (unsigned)__cvta_generic_to_shared(p);
}
__device__ __forceinline__ void ldm_x4(unsigned& r0, unsigned& r1, unsigned& r2, unsigned& r3,
                                       unsigned addr) {
    asm volatile("ldmatrix.sync.aligned.m8n8.x4.shared.b16 {%0,%1,%2,%3},[%4];\n"
                 : "=r"(r0), "=r"(r1), "=r"(r2), "=r"(r3) : "r"(addr));
}
__device__ __forceinline__ void ldm_x2(unsigned& r0, unsigned& r1, unsigned addr) {
    asm volatile("ldmatrix.sync.aligned.m8n8.x2.shared.b16 {%0,%1},[%2];\n"
                 : "=r"(r0), "=r"(r1) : "r"(addr));
}
__device__ __forceinline__ void mma16816(float* c, unsigned a0, unsigned a1, unsigned a2,
                                         unsigned a3, unsigned b0, unsigned b1) {
    asm volatile(
        "mma.sync.aligned.m16n8k16.row.col.f32.bf16.bf16.f32 "
        "{%0,%1,%2,%3},{%4,%5,%6,%7},{%8,%9},{%0,%1,%2,%3};\n"
        : "+f"(c[0]), "+f"(c[1]), "+f"(c[2]), "+f"(c[3])
        : "r"(a0), "r"(a1), "r"(a2), "r"(a3), "r"(b0), "r"(b1));
}
__device__ __forceinline__ void mma3(float* c, const unsigned* ah, const unsigned* al,
                                     unsigned bh0, unsigned bh1, unsigned bl0, unsigned bl1) {
    mma16816(c, ah[0], ah[1], ah[2], ah[3], bh0, bh1);
    mma16816(c, ah[0], ah[1], ah[2], ah[3], bl0, bl1);
    mma16816(c, al[0], al[1], al[2], al[3], bh0, bh1);
}
__device__ __forceinline__ unsigned pack2(float x, float y) {
    bf162 t; t.x = __float2bfloat16(x); t.y = __float2bfloat16(y);
    return *(unsigned*)&t;
}
__device__ __forceinline__ void split2(float x, float y, unsigned& hi, unsigned& lo) {
    bf162 h; h.x = __float2bfloat16(x); h.y = __float2bfloat16(y);
    bf162 l; l.x = __float2bfloat16(x - __bfloat162float(h.x));
    l.y = __float2bfloat16(y - __bfloat162float(h.y));
    hi = *(unsigned*)&h; lo = *(unsigned*)&l;
}

// ---------------- elementwise split fp32 -> (hi, lo) bf16 ----------------
__global__ __launch_bounds__(256) void conv_split(const float* __restrict__ X,
                                                  bf16* __restrict__ Xh, bf16* __restrict__ Xl,
                                                  int n4)
{
    int i = blockIdx.x * 256 + threadIdx.x;
    if (i >= n4) return;
    float4 v = *(const float4*)&X[(size_t)i * 4];
    unsigned h0, l0, h1, l1;
    split2(v.x, v.y, h0, l0);
    split2(v.z, v.w, h1, l1);
    float2 ho, lo;
    ((unsigned*)&ho)[0] = h0; ((unsigned*)&ho)[1] = h1;
    ((unsigned*)&lo)[0] = l0; ((unsigned*)&lo)[1] = l1;
    *(float2*)&Xh[(size_t)i * 4] = ho;
    *(float2*)&Xl[(size_t)i * 4] = lo;
}

// ---------------- transpose + split: W[K][N] -> T[N][K] ----------------
__global__ __launch_bounds__(256) void convT(const float* __restrict__ W,
                                             bf16* __restrict__ Th, bf16* __restrict__ Tl,
                                             int K, int N)
{
    __shared__ float t[32][33];
    const int tx = threadIdx.x & 31;
    const int ty = threadIdx.x >> 5;      // 0..7
    const int n0 = blockIdx.x * 32;
    const int k0 = blockIdx.y * 32;
#pragma unroll
    for (int i = 0; i < 4; i++) {
        int r = ty + 8 * i;
        t[r][tx] = W[(size_t)(k0 + r) * N + n0 + tx];
    }
    __syncthreads();
#pragma unroll
    for (int i = 0; i < 4; i++) {
        int n = ty + 8 * i;
        float v = t[tx][n];
        bf16 h = __float2bfloat16(v);
        Th[(size_t)(n0 + n) * K + k0 + tx] = h;
        Tl[(size_t)(n0 + n) * K + k0 + tx] = __float2bfloat16(v - __bfloat162float(h));
    }
}

// ---------------- GEMM: pure-bf16x3 mainloop, multi-mode epilogue ----------------
// A split [M][K], B split [N][K]. 128x128 tile, k-step 32, 8 warps (2x4), warp 64x32.
// mode 0: fp32 out (optional bias)
// mode 1: bias + per-head(128col) rmsnorm(nw) + split bf16 out [M][N]
// mode 2: bias + split bf16 out TRANSPOSED [N][M] (stride vt_stride = M)
__global__ __launch_bounds__(256) void gemm_x3(
    const bf16* __restrict__ Ahi, const bf16* __restrict__ Alo,
    const bf16* __restrict__ Bhi, const bf16* __restrict__ Blo,
    const float* __restrict__ bias, const float* __restrict__ nw,
    float* __restrict__ Cf, bf16* __restrict__ Chi, bf16* __restrict__ Clo,
    int M, int N, int K, int mode, int vt_stride)
{
    __shared__ unsigned sAhi[128 * 20], sAlo[128 * 20];
    __shared__ unsigned sBhi[128 * 20], sBlo[128 * 20];
    __shared__ float ssq[128];

    const int tid  = threadIdx.x;
    const int lane = tid & 31;
    const int warp = tid >> 5;
    const int wm   = warp >> 2;
    const int wn   = warp & 3;
    const int g    = lane >> 2;
    const int th   = lane & 3;
    const int m0   = blockIdx.y * 128;
    const int n0   = blockIdx.x * 128;

    float acc[4][4][4];
#pragma unroll
    for (int i = 0; i < 4; i++)
#pragma unroll
        for (int j = 0; j < 4; j++)
#pragma unroll
            for (int c = 0; c < 4; c++) acc[i][j][c] = 0.f;

    // prefetch regs: per thread 2 float4 per buffer
    float4 pAh[2], pAl[2], pBh[2], pBl[2];
#pragma unroll
    for (int l = 0; l < 2; l++) {
        int gi = l * 256 + tid;
        int row = gi >> 2, seg = gi & 3;
        pAh[l] = *(const float4*)&Ahi[(size_t)(m0 + row) * K + seg * 8];
        pAl[l] = *(const float4*)&Alo[(size_t)(m0 + row) * K + seg * 8];
        pBh[l] = *(const float4*)&Bhi[(size_t)(n0 + row) * K + seg * 8];
        pBl[l] = *(const float4*)&Blo[(size_t)(n0 + row) * K + seg * 8];
    }

    const int nK = K / 32;
    for (int kt = 0; kt < nK; kt++) {
#pragma unroll
        for (int l = 0; l < 2; l++) {
            int gi = l * 256 + tid;
            int row = gi >> 2, seg = gi & 3;
            int o = row * 20 + seg * 4;
            *(float2*)&sAhi[o]     = make_float2(pAh[l].x, pAh[l].y);
            *(float2*)&sAhi[o + 2] = make_float2(pAh[l].z, pAh[l].w);
            *(float2*)&sAlo[o]     = make_float2(pAl[l].x, pAl[l].y);
            *(float2*)&sAlo[o + 2] = make_float2(pAl[l].z, pAl[l].w);
            *(float2*)&sBhi[o]     = make_float2(pBh[l].x, pBh[l].y);
            *(float2*)&sBhi[o + 2] = make_float2(pBh[l].z, pBh[l].w);
            *(float2*)&sBlo[o]     = make_float2(pBl[l].x, pBl[l].y);
            *(float2*)&sBlo[o + 2] = make_float2(pBl[l].z, pBl[l].w);
        }
        __syncthreads();
        if (kt + 1 < nK) {
            int kk = (kt + 1) * 32;
#pragma unroll
            for (int l = 0; l < 2; l++) {
                int gi = l * 256 + tid;
                int row = gi >> 2, seg = gi & 3;
                pAh[l] = *(const float4*)&Ahi[(size_t)(m0 + row) * K + kk + seg * 8];
                pAl[l] = *(const float4*)&Alo[(size_t)(m0 + row) * K + kk + seg * 8];
                pBh[l] = *(const float4*)&Bhi[(size_t)(n0 + row) * K + kk + seg * 8];
                pBl[l] = *(const float4*)&Blo[(size_t)(n0 + row) * K + kk + seg * 8];
            }
        }
#pragma unroll
        for (int ks = 0; ks < 2; ks++) {
            unsigned ahi[4][4], alo[4][4];
            const int rowl = wm * 64 + (lane & 15);
            const int colu = ks * 8 + (lane >> 4) * 4;
#pragma unroll
            for (int mt = 0; mt < 4; mt++) {
                ldm_x4(ahi[mt][0], ahi[mt][1], ahi[mt][2], ahi[mt][3],
                       smaddr(&sAhi[(rowl + mt * 16) * 20 + colu]));
                ldm_x4(alo[mt][0], alo[mt][1], alo[mt][2], alo[mt][3],
                       smaddr(&sAlo[(rowl + mt * 16) * 20 + colu]));
            }
            const int rowb = lane & 7;
            const int colb = ks * 8 + ((lane >> 3) & 1) * 4;
#pragma unroll
            for (int nt = 0; nt < 4; nt++) {
                unsigned bh0, bh1, bl0, bl1;
                ldm_x2(bh0, bh1, smaddr(&sBhi[(wn * 32 + nt * 8 + rowb) * 20 + colb]));
                ldm_x2(bl0, bl1, smaddr(&sBlo[(wn * 32 + nt * 8 + rowb) * 20 + colb]));
#pragma unroll
                for (int mt = 0; mt < 4; mt++)
                    mma3(acc[mt][nt], ahi[mt], alo[mt], bh0, bh1, bl0, bl1);
            }
        }
        __syncthreads();
    }

    // ---- bias ----
    if (bias) {
#pragma unroll
        for (int nt = 0; nt < 4; nt++) {
            int cc = n0 + wn * 32 + nt * 8 + th * 2;
            float b0 = bias[cc], b1 = bias[cc + 1];
#pragma unroll
            for (int mt = 0; mt < 4; mt++) {
                acc[mt][nt][0] += b0; acc[mt][nt][1] += b1;
                acc[mt][nt][2] += b0; acc[mt][nt][3] += b1;
            }
        }
    }

    if (mode == 0) {
#pragma unroll
        for (int mt = 0; mt < 4; mt++) {
            int r0 = m0 + wm * 64 + mt * 16 + g;
#pragma unroll
            for (int nt = 0; nt < 4; nt++) {
                int cc = n0 + wn * 32 + nt * 8 + th * 2;
                *(float2*)&Cf[(size_t)r0 * N + cc] = make_float2(acc[mt][nt][0], acc[mt][nt][1]);
                *(float2*)&Cf[(size_t)(r0 + 8) * N + cc] = make_float2(acc[mt][nt][2], acc[mt][nt][3]);
            }
        }
    } else if (mode == 1) {
        // per-row sum of squares over this CTA's 128 cols (= one head)
        if (tid < 128) ssq[tid] = 0.f;
        __syncthreads();
#pragma unroll
        for (int mt = 0; mt < 4; mt++) {
            int rl = wm * 64 + mt * 16 + g;
            float p0 = 0.f, p1 = 0.f;
#pragma unroll
            for (int nt = 0; nt < 4; nt++) {
                p0 += acc[mt][nt][0] * acc[mt][nt][0] + acc[mt][nt][1] * acc[mt][nt][1];
                p1 += acc[mt][nt][2] * acc[mt][nt][2] + acc[mt][nt][3] * acc[mt][nt][3];
            }
            atomicAdd(&ssq[rl], p0);
            atomicAdd(&ssq[rl + 8], p1);
        }
        __syncthreads();
#pragma unroll
        for (int mt = 0; mt < 4; mt++) {
            int rl = wm * 64 + mt * 16 + g;
            float inv0 = rsqrtf(ssq[rl] * (1.0f / HD) + EPS);
            float inv1 = rsqrtf(ssq[rl + 8] * (1.0f / HD) + EPS);
#pragma unroll
            for (int nt = 0; nt < 4; nt++) {
                int col = wn * 32 + nt * 8 + th * 2;   // col within head
                float w0 = nw[col], w1 = nw[col + 1];
                unsigned h, l;
                split2(acc[mt][nt][0] * inv0 * w0, acc[mt][nt][1] * inv0 * w1, h, l);
                *(unsigned*)&Chi[(size_t)(m0 + rl) * N + n0 + col] = h;
                *(unsigned*)&Clo[(size_t)(m0 + rl) * N + n0 + col] = l;
                split2(acc[mt][nt][2] * inv1 * w0, acc[mt][nt][3] * inv1 * w1, h, l);
                *(unsigned*)&Chi[(size_t)(m0 + rl + 8) * N + n0 + col] = h;
                *(unsigned*)&Clo[(size_t)(m0 + rl + 8) * N + n0 + col] = l;
            }
        }
    } else {
        // mode 2: transposed split store: T[n][m], stride vt_stride
#pragma unroll
        for (int mt = 0; mt < 4; mt++) {
            int r0 = m0 + wm * 64 + mt * 16 + g;
#pragma unroll
            for (int nt = 0; nt < 4; nt++) {
                int cn = n0 + wn * 32 + nt * 8 + th * 2;
#pragma unroll
                for (int j = 0; j < 2; j++) {
                    float v0 = acc[mt][nt][j];        // row r0
                    float v1 = acc[mt][nt][2 + j];    // row r0+8
                    bf16 h0 = __float2bfloat16(v0);
                    bf16 h1 = __float2bfloat16(v1);
                    Chi[(size_t)(cn + j) * vt_stride + r0] = h0;
                    Chi[(size_t)(cn + j) * vt_stride + r0 + 8] = h1;
                    Clo[(size_t)(cn + j) * vt_stride + r0] =
                        __float2bfloat16(v0 - __bfloat162float(h0));
                    Clo[(size_t)(cn + j) * vt_stride + r0 + 8] =
                        __float2bfloat16(v1 - __bfloat162float(h1));
                }
            }
        }
    }
}

// ---------------- flash attention, pre-split bf16 inputs ----------------
#define FL_SMEM_U32 (2 * (128 * 68) + 2 * (32 * 68) + 2 * (128 * 20))
#define FL_SMEM_BYTES (FL_SMEM_U32 * 4)

__global__ __launch_bounds__(128) void flash_x3b(
    const bf16* __restrict__ Qhi, const bf16* __restrict__ Qlo,
    const bf16* __restrict__ Khi, const bf16* __restrict__ Klo,
    const bf16* __restrict__ VThi, const bf16* __restrict__ VTlo,
    const float* __restrict__ mask,
    bf16* __restrict__ AOhi, bf16* __restrict__ AOlo)
{
    extern __shared__ unsigned smbuf[];
    unsigned* sQhi = smbuf;                    // [128][68]
    unsigned* sQlo = sQhi + 128 * 68;
    unsigned* sKhi = sQlo + 128 * 68;          // [32][68]
    unsigned* sKlo = sKhi + 32 * 68;
    unsigned* sVhi = sKlo + 32 * 68;           // [128][20]  (rows=hd, cols=kv pairs)
    unsigned* sVlo = sVhi + 128 * 20;

    const int h  = blockIdx.y;
    const int kh = h >> 2;
    const int q0 = blockIdx.x * 128;
    const int tid  = threadIdx.x;
    const int lane = tid & 31;
    const int wm   = tid >> 5;
    const int g    = lane >> 2;
    const int th   = lane & 3;

    // Q tile: 128 rows x 128 bf16 (hi+lo)
#pragma unroll
    for (int l = 0; l < 16; l++) {
        int gi = l * 128 + tid;
        int row = gi >> 4, c8 = gi & 15;
        float4 vh = *(const float4*)&Qhi[(size_t)(q0 + row) * (NH * HD) + h * HD + c8 * 8];
        float4 vl = *(const float4*)&Qlo[(size_t)(q0 + row) * (NH * HD) + h * HD + c8 * 8];
        *(float4*)&sQhi[row * 68 + c8 * 4] = vh;
        *(float4*)&sQlo[row * 68 + c8 * 4] = vl;
    }

    const float scale = 0.08838834764831845f;
    float o[2][16][4];
    float m_i[4], l_i[4];
#pragma unroll
    for (int mt = 0; mt < 2; mt++)
#pragma unroll
        for (int nt = 0; nt < 16; nt++)
#pragma unroll
            for (int c = 0; c < 4; c++) o[mt][nt][c] = 0.f;
#pragma unroll
    for (int i = 0; i < 4; i++) { m_i[i] = -INFINITY; l_i[i] = 0.f; }

    for (int e0 = 0; e0 < S_E; e0 += 32) {
        __syncthreads();
        // K tile [32][128] + V tile [128][32] (both hi/lo)
#pragma unroll
        for (int l = 0; l < 4; l++) {
            int gi = l * 128 + tid;
            int krow = gi >> 4, kc8 = gi & 15;
            float4 vh = *(const float4*)&Khi[(size_t)(e0 + krow) * (NKV * HD) + kh * HD + kc8 * 8];
            float4 vl = *(const float4*)&Klo[(size_t)(e0 + krow) * (NKV * HD) + kh * HD + kc8 * 8];
            *(float4*)&sKhi[krow * 68 + kc8 * 4] = vh;
            *(float4*)&sKlo[krow * 68 + kc8 * 4] = vl;

            int vrow = gi >> 2, vc4 = gi & 3;
            float4 wh = *(const float4*)&VThi[(size_t)(kh * HD + vrow) * S_E + e0 + vc4 * 8];
            float4 wl = *(const float4*)&VTlo[(size_t)(kh * HD + vrow) * S_E + e0 + vc4 * 8];
            int ov = vrow * 20 + vc4 * 4;
            *(float2*)&sVhi[ov]     = make_float2(wh.x, wh.y);
            *(float2*)&sVhi[ov + 2] = make_float2(wh.z, wh.w);
            *(float2*)&sVlo[ov]     = make_float2(wl.x, wl.y);
            *(float2*)&sVlo[ov + 2] = make_float2(wl.z, wl.w);
        }
        __syncthreads();

        // S = Q K^T
        float s[2][4][4];
#pragma unroll
        for (int mt = 0; mt < 2; mt++)
#pragma unroll
            for (int nt = 0; nt < 4; nt++)
#pragma unroll
                for (int c = 0; c < 4; c++) s[mt][nt][c] = 0.f;

#pragma unroll
        for (int ks = 0; ks < 8; ks++) {
            unsigned ahi[2][4], alo[2][4];
            const int rowl = wm * 32 + (lane & 15);
            const int colu = ks * 8 + (lane >> 4) * 4;
#pragma unroll
            for (int mt = 0; mt < 2; mt++) {
                ldm_x4(ahi[mt][0], ahi[mt][1], ahi[mt][2], ahi[mt][3],
                       smaddr(&sQhi[(rowl + mt * 16) * 68 + colu]));
                ldm_x4(alo[mt][0], alo[mt][1], alo[mt][2], alo[mt][3],
                       smaddr(&sQlo[(rowl + mt * 16) * 68 + colu]));
            }
            const int rowb = lane & 7;
            const int colb = ks * 8 + ((lane >> 3) & 1) * 4;
#pragma unroll
            for (int nt = 0; nt < 4; nt++) {
                unsigned bh0, bh1, bl0, bl1;
                ldm_x2(bh0, bh1, smaddr(&sKhi[(nt * 8 + rowb) * 68 + colb]));
                ldm_x2(bl0, bl1, smaddr(&sKlo[(nt * 8 + rowb) * 68 + colb]));
#pragma unroll
                for (int mt = 0; mt < 2; mt++)
                    mma3(s[mt][nt], ahi[mt], alo[mt], bh0, bh1, bl0, bl1);
            }
        }

        // online softmax
#pragma unroll
        for (int mt = 0; mt < 2; mt++) {
            const int r0 = q0 + wm * 32 + mt * 16 + g;
#pragma unroll
            for (int nt = 0; nt < 4; nt++) {
                const int cb = e0 + nt * 8 + th * 2;
                float2 mk0 = *(const float2*)&mask[(size_t)r0 * S_E + cb];
                float2 mk1 = *(const float2*)&mask[(size_t)(r0 + 8) * S_E + cb];
                s[mt][nt][0] = s[mt][nt][0] * scale + mk0.x;
                s[mt][nt][1] = s[mt][nt][1] * scale + mk0.y;
                s[mt][nt][2] = s[mt][nt][2] * scale + mk1.x;
                s[mt][nt][3] = s[mt][nt][3] * scale + mk1.y;
            }
            float mx0 = -INFINITY, mx1 = -INFINITY;
#pragma unroll
            for (int nt = 0; nt < 4; nt++) {
                mx0 = fmaxf(mx0, fmaxf(s[mt][nt][0], s[mt][nt][1]));
                mx1 = fmaxf(mx1, fmaxf(s[mt][nt][2], s[mt][nt][3]));
            }
            mx0 = fmaxf(mx0, __shfl_xor_sync(0xffffffffu, mx0, 1));
            mx0 = fmaxf(mx0, __shfl_xor_sync(0xffffffffu, mx0, 2));
            mx1 = fmaxf(mx1, __shfl_xor_sync(0xffffffffu, mx1, 1));
            mx1 = fmaxf(mx1, __shfl_xor_sync(0xffffffffu, mx1, 2));
            float mn0 = fmaxf(m_i[mt * 2 + 0], mx0);
            float mn1 = fmaxf(m_i[mt * 2 + 1], mx1);
            float cr0 = __expf(m_i[mt * 2 + 0] - mn0);
            float cr1 = __expf(m_i[mt * 2 + 1] - mn1);
            m_i[mt * 2 + 0] = mn0;
            m_i[mt * 2 + 1] = mn1;
            float sm0 = 0.f, sm1 = 0.f;
#pragma unroll
            for (int nt = 0; nt < 4; nt++) {
                s[mt][nt][0] = __expf(s[mt][nt][0] - mn0);
                s[mt][nt][1] = __expf(s[mt][nt][1] - mn0);
                s[mt][nt][2] = __expf(s[mt][nt][2] - mn1);
                s[mt][nt][3] = __expf(s[mt][nt][3] - mn1);
                sm0 += s[mt][nt][0] + s[mt][nt][1];
                sm1 += s[mt][nt][2] + s[mt][nt][3];
            }
            sm0 += __shfl_xor_sync(0xffffffffu, sm0, 1);
            sm0 += __shfl_xor_sync(0xffffffffu, sm0, 2);
            sm1 += __shfl_xor_sync(0xffffffffu, sm1, 1);
            sm1 += __shfl_xor_sync(0xffffffffu, sm1, 2);
            l_i[mt * 2 + 0] = l_i[mt * 2 + 0] * cr0 + sm0;
            l_i[mt * 2 + 1] = l_i[mt * 2 + 1] * cr1 + sm1;
#pragma unroll
            for (int nt = 0; nt < 16; nt++) {
                o[mt][nt][0] *= cr0;
                o[mt][nt][1] *= cr0;
                o[mt][nt][2] *= cr1;
                o[mt][nt][3] *= cr1;
            }
        }

        // O += P V
#pragma unroll
        for (int ks2 = 0; ks2 < 2; ks2++) {
            unsigned phi[2][4], plo[2][4];
#pragma unroll
            for (int mt = 0; mt < 2; mt++) {
                const float* sa = s[mt][2 * ks2];
                const float* sb = s[mt][2 * ks2 + 1];
                split2(sa[0], sa[1], phi[mt][0], plo[mt][0]);
                split2(sa[2], sa[3], phi[mt][1], plo[mt][1]);
                split2(sb[0], sb[1], phi[mt][2], plo[mt][2]);
                split2(sb[2], sb[3], phi[mt][3], plo[mt][3]);
            }
            const int rowv = lane & 7;
            const int colv = ks2 * 8 + ((lane >> 3) & 1) * 4;
#pragma unroll
            for (int nt2 = 0; nt2 < 16; nt2++) {
                unsigned vh0, vh1, vl0, vl1;
                ldm_x2(vh0, vh1, smaddr(&sVhi[(nt2 * 8 + rowv) * 20 + colv]));
                ldm_x2(vl0, vl1, smaddr(&sVlo[(nt2 * 8 + rowv) * 20 + colv]));
#pragma unroll
                for (int mt = 0; mt < 2; mt++)
                    mma3(o[mt][nt2], phi[mt], plo[mt], vh0, vh1, vl0, vl1);
            }
        }
    }

    // epilogue: split bf16 store
#pragma unroll
    for (int mt = 0; mt < 2; mt++) {
        const int r0 = q0 + wm * 32 + mt * 16 + g;
        const float inv0 = 1.0f / l_i[mt * 2 + 0];
        const float inv1 = 1.0f / l_i[mt * 2 + 1];
#pragma unroll
        for (int nt2 = 0; nt2 < 16; nt2++) {
            const int cc = h * HD + nt2 * 8 + th * 2;
            unsigned hh, ll;
            split2(o[mt][nt2][0] * inv0, o[mt][nt2][1] * inv0, hh, ll);
            *(unsigned*)&AOhi[(size_t)r0 * (NH * HD) + cc] = hh;
            *(unsigned*)&AOlo[(size_t)r0 * (NH * HD) + cc] = ll;
            split2(o[mt][nt2][2] * inv1, o[mt][nt2][3] * inv1, hh, ll);
            *(unsigned*)&AOhi[(size_t)(r0 + 8) * (NH * HD) + cc] = hh;
            *(unsigned*)&AOlo[(size_t)(r0 + 8) * (NH * HD) + cc] = ll;
        }
    }
}

// ---------------- launch ----------------
#define SYM(p, s) cudaGetSymbolAddress((void**)&p, s)

extern "C" void kernel_launch(void* const* d_in, const int* in_sizes, int n_in,
                              void* d_out, int out_size)
{
    const float* hs   = (const float*)d_in[0];
    const float* ehs  = (const float*)d_in[1];
    const float* mask = (const float*)d_in[2];
    const float* Wq   = (const float*)d_in[3];
    const float* bq   = (const float*)d_in[4];
    const float* Wk   = (const float*)d_in[5];
    const float* bk   = (const float*)d_in[6];
    const float* Wv   = (const float*)d_in[7];
    const float* bv   = (const float*)d_in[8];
    const float* Wo   = (const float*)d_in[9];
    const float* qn   = (const float*)d_in[10];
    const float* kn   = (const float*)d_in[11];
    float* out = (float*)d_out;

    bf16 *hsH, *hsL, *ehsH, *ehsL, *WqTH, *WqTL, *WkTH, *WkTL, *WvTH, *WvTL, *WoTH, *WoTL;
    bf16 *QH, *QL, *KH, *KL, *VTH, *VTL, *AOH, *AOL;
    SYM(hsH, g_hsH);  SYM(hsL, g_hsL);
    SYM(ehsH, g_ehsH); SYM(ehsL, g_ehsL);
    SYM(WqTH, g_WqTH); SYM(WqTL, g_WqTL);
    SYM(WkTH, g_WkTH); SYM(WkTL, g_WkTL);
    SYM(WvTH, g_WvTH); SYM(WvTL, g_WvTL);
    SYM(WoTH, g_WoTH); SYM(WoTL, g_WoTL);
    SYM(QH, g_QH); SYM(QL, g_QL);
    SYM(KH, g_KH); SYM(KL, g_KL);
    SYM(VTH, g_VTH); SYM(VTL, g_VTL);
    SYM(AOH, g_AOH); SYM(AOL, g_AOL);

    cudaFuncSetAttribute(flash_x3b, cudaFuncAttributeMaxDynamicSharedMemorySize, FL_SMEM_BYTES);

    // pre-split activations
    conv_split<<<(S_Q * H / 4 + 255) / 256, 256>>>(hs, hsH, hsL, S_Q * H / 4);
    conv_split<<<(S_E * H / 4 + 255) / 256, 256>>>(ehs, ehsH, ehsL, S_E * H / 4);
    // pre-split + transpose weights -> [N][K]
    convT<<<dim3(H / 32, H / 32), 256>>>(Wq, WqTH, WqTL, H, H);
    convT<<<dim3(512 / 32, H / 32), 256>>>(Wk, WkTH, WkTL, H, 512);
    convT<<<dim3(512 / 32, H / 32), 256>>>(Wv, WvTH, WvTL, H, 512);
    convT<<<dim3(H / 32, H / 32), 256>>>(Wo, WoTH, WoTL, H, H);

    // projections (rmsnorm fused for Q/K; V transposed)
    gemm_x3<<<dim3(H / 128, S_Q / 128), 256>>>(hsH, hsL, WqTH, WqTL, bq, qn,
                                               nullptr, QH, QL, S_Q, H, H, 1, 0);
    gemm_x3<<<dim3(512 / 128, S_E / 128), 256>>>(ehsH, ehsL, WkTH, WkTL, bk, kn,
                                                 nullptr, KH, KL, S_E, 512, H, 1, 0);
    gemm_x3<<<dim3(512 / 128, S_E / 128), 256>>>(ehsH, ehsL, WvTH, WvTL, bv, nullptr,
                                                 nullptr, VTH, VTL, S_E, 512, H, 2, S_E);

    // attention
    flash_x3b<<<dim3(S_Q / 128, NH), 128, FL_SMEM_BYTES>>>(QH, QL, KH, KL, VTH, VTL,
                                                           mask, AOH, AOL);

    // output projection (fp32 out, no bias)
    gemm_x3<<<dim3(H / 128, S_Q / 128), 256>>>(AOH, AOL, WoTH, WoTL, nullptr, nullptr,
                                               out, nullptr, nullptr, S_Q, H, NH * HD, 0, 0);
}